// round 15
// baseline (speedup 1.0000x reference)
#include <cuda_runtime.h>
#include <cuda_fp16.h>
#include <math.h>
#include <stdint.h>

#define L_SEQ   2048
#define DMODEL  2048
#define NHEADS  16
#define HDIM    128
#define WINDOW  512
#define BROWS   4096   // B * L
#define KDIM    2048

typedef __half h16;

// ================= scratch =================
__device__ float g_cs[L_SEQ * 64];          // (cos,sin) interleaved
__device__ h16 g_xh[BROWS * DMODEL];
__device__ h16 g_xl[BROWS * DMODEL];
__device__ h16 g_qh[BROWS * DMODEL];
__device__ h16 g_ql[BROWS * DMODEL];
__device__ h16 g_kh[BROWS * HDIM];
__device__ h16 g_vh[BROWS * HDIM];
__device__ h16 g_ath[BROWS * DMODEL];
__device__ h16 g_atl[BROWS * DMODEL];
__device__ h16 g_wqt_h[DMODEL * KDIM];
__device__ h16 g_wot_h[DMODEL * KDIM];
__device__ h16 g_wkvt_h[256 * KDIM];

// ================= helpers =================
__device__ __forceinline__ uint32_t smem_u32(const void* p) {
    uint32_t a;
    asm("{ .reg .u64 t; cvta.to.shared.u64 t, %1; cvt.u32.u64 %0, t; }" : "=r"(a) : "l"(p));
    return a;
}
#define CP_ASYNC16(saddr, gptr) \
    asm volatile("cp.async.cg.shared.global [%0], [%1], 16;" :: "r"(saddr), "l"(gptr))
#define CP_COMMIT()  asm volatile("cp.async.commit_group;" ::: "memory")
#define CP_WAIT0()   asm volatile("cp.async.wait_group 0;" ::: "memory")
#define CP_WAIT1()   asm volatile("cp.async.wait_group 1;" ::: "memory")
#define CP_WAIT2()   asm volatile("cp.async.wait_group 2;" ::: "memory")

#define LDMATRIX_X4(r0, r1, r2, r3, addr) \
    asm volatile("ldmatrix.sync.aligned.m8n8.x4.shared.b16 {%0,%1,%2,%3}, [%4];" \
        : "=r"(r0), "=r"(r1), "=r"(r2), "=r"(r3) : "r"(addr))

#define LDMATRIX_X4_T(r0, r1, r2, r3, addr) \
    asm volatile("ldmatrix.sync.aligned.m8n8.x4.trans.shared.b16 {%0,%1,%2,%3}, [%4];" \
        : "=r"(r0), "=r"(r1), "=r"(r2), "=r"(r3) : "r"(addr))

#define MMA_F16(c, a, b) \
    asm volatile("mma.sync.aligned.m16n8k16.row.col.f32.f16.f16.f32 " \
        "{%0,%1,%2,%3}, {%4,%5,%6,%7}, {%8,%9}, {%0,%1,%2,%3};" \
        : "+f"((c)[0]), "+f"((c)[1]), "+f"((c)[2]), "+f"((c)[3]) \
        : "r"((a)[0]), "r"((a)[1]), "r"((a)[2]), "r"((a)[3]), "r"((b)[0]), "r"((b)[1]))

__device__ __forceinline__ uint32_t pack_split(float a, float b, uint32_t& lo) {
    __half2 h = __floats2half2_rn(a, b);
    __half2 l = __floats2half2_rn(a - __low2float(h), b - __high2float(h));
    lo = *(uint32_t*)&l;
    return *(uint32_t*)&h;
}

// ================= prep kernels =================
__global__ void prep_kernel(const float* __restrict__ in, int n) {
    int idx = blockIdx.x * blockDim.x + threadIdx.x;
    if (idx < L_SEQ * 32) {
        int pos = idx >> 5;
        int i = idx & 31;
        double inv = exp(-log(10000.0) * ((double)(2 * i) / 64.0));
        double th = (double)pos * inv;
        g_cs[pos * 64 + i * 2 + 0] = (float)cos(th);
        g_cs[pos * 64 + i * 2 + 1] = (float)sin(th);
    }
    if (idx < n) {
        float v = in[idx];
        h16 h = __float2half_rn(v);
        g_xh[idx] = h;
        g_xl[idx] = __float2half_rn(v - __half2float(h));
    }
}

__global__ void thalf_kernel(const float* __restrict__ W,
                             h16* __restrict__ Th, int N, int ro) {
    __shared__ float tile[32][33];
    int n0 = blockIdx.x * 32, k0 = blockIdx.y * 32;
    int tx = threadIdx.x, ty = threadIdx.y;
    #pragma unroll
    for (int i = ty; i < 32; i += 8)
        tile[i][tx] = W[(size_t)(k0 + i) * N + n0 + tx];
    __syncthreads();
    #pragma unroll
    for (int i = ty; i < 32; i += 8)
        Th[(size_t)(ro + n0 + i) * KDIM + k0 + tx] = __float2half_rn(tile[tx][i]);
}

__global__ void thalf_kv_kernel(const float* __restrict__ Wk,
                                const float* __restrict__ Wv) {
    __shared__ float tile[32][33];
    const float* W = blockIdx.z ? Wv : Wk;
    int ro = blockIdx.z ? 128 : 0;
    int n0 = blockIdx.x * 32, k0 = blockIdx.y * 32;
    int tx = threadIdx.x, ty = threadIdx.y;
    #pragma unroll
    for (int i = ty; i < 32; i += 8)
        tile[i][tx] = W[(size_t)(k0 + i) * HDIM + n0 + tx];
    __syncthreads();
    #pragma unroll
    for (int i = ty; i < 32; i += 8)
        g_wkvt_h[(size_t)(ro + n0 + i) * KDIM + k0 + tx] = __float2half_rn(tile[tx][i]);
}

// ===== mma.sync fp16 2-pass GEMM, CTA tile 128x64, 3 CTAs/SM (24 warps) =====
// per stage: A-hi 8KB + A-lo 8KB + B 4KB = 20KB; 3 stages = 60KB.
// warp tile 32x32 striped: col(nf) = wn*16 + (nf&1)*8 + (nf>>1)*32.
template <bool QKV>
__global__ void __launch_bounds__(256, 3)
gemm_kernel(const float* __restrict__ bias, float* __restrict__ Cout) {
    extern __shared__ char smem[];
    const uint32_t smb = smem_u32(smem);
    const uint32_t STAGE = 20480;
    const int tid = threadIdx.x;
    const int wid = tid >> 5;
    const int lane = tid & 31;
    const int wm = wid >> 1;          // 0..3 : 32 rows each
    const int wn = wid & 1;           // 0..1 : 16-col stripes
    const uint32_t midx = lane >> 3;
    const uint32_t rsel = lane & 7;

    const int m0 = blockIdx.y * 128;
    const h16* Ah = QKV ? g_xh : g_ath;
    const h16* Al = QKV ? g_xl : g_atl;
    const h16* Bh;
    int n0;
    h16 *OutH = nullptr, *OutL = nullptr;
    int strideO = 0, colBase = 0;
    bool do_rope = false, do_scale = false;
    if (QKV) {
        if ((int)blockIdx.x < 32) {
            Bh = g_wqt_h; n0 = blockIdx.x * 64;
            OutH = g_qh; OutL = g_ql; strideO = DMODEL; colBase = n0;
            do_rope = (n0 & 64) == 0; do_scale = true;
        } else {
            int t = blockIdx.x - 32;          // 0,1 -> K ; 2,3 -> V
            Bh = g_wkvt_h; n0 = t * 64;
            OutH = (t < 2) ? g_kh : g_vh;
            OutL = nullptr; strideO = HDIM; colBase = (t & 1) * 64;
            do_rope = (t == 0);
        }
    } else {
        Bh = g_wot_h; n0 = blockIdx.x * 64;
    }

    const h16* srcA_h = Ah + (size_t)m0 * KDIM;
    const h16* srcA_l = Al + (size_t)m0 * KDIM;
    const h16* srcB   = Bh + (size_t)n0 * KDIM;

    const int fr = tid >> 2;                 // 0..63
    const uint32_t fkt = (uint32_t)(tid & 3);
    const int fc0 = (tid & 3) * 8;

    auto fill = [&](int kc, uint32_t sbase) {
        #pragma unroll
        for (int half = 0; half < 2; half++) {
            int rr = fr + half * 64;
            uint32_t off = ((uint32_t)(rr >> 3) * 4 + fkt) * 128
                         + ((uint32_t)((rr & 7) ^ fkt) * 16);
            CP_ASYNC16(sbase + off,        srcA_h + (size_t)rr * KDIM + kc * 32 + fc0);
            CP_ASYNC16(sbase + 8192 + off, srcA_l + (size_t)rr * KDIM + kc * 32 + fc0);
        }
        {
            uint32_t off = ((uint32_t)(fr >> 3) * 4 + fkt) * 128
                         + ((uint32_t)((fr & 7) ^ fkt) * 16);
            CP_ASYNC16(sbase + 16384 + off, srcB + (size_t)fr * KDIM + kc * 32 + fc0);
        }
    };

    float acc[2][4][4];
    #pragma unroll
    for (int i = 0; i < 2; i++)
        #pragma unroll
        for (int j = 0; j < 4; j++)
            #pragma unroll
            for (int c = 0; c < 4; c++) acc[i][j][c] = 0.0f;

    fill(0, smb);          CP_COMMIT();
    fill(1, smb + STAGE);  CP_COMMIT();

    const int NK = KDIM / 32;
    for (int kc = 0; kc < NK; kc++) {
        if (kc + 1 < NK) CP_WAIT1(); else CP_WAIT0();
        __syncthreads();
        if (kc + 2 < NK) {
            fill(kc + 2, smb + ((kc + 2) % 3) * STAGE);
            CP_COMMIT();
        }

        const uint32_t sb = smb + (kc % 3) * STAGE;
        const uint32_t aBaseH = sb;
        const uint32_t aBaseL = sb + 8192;
        const uint32_t bBase  = sb + 16384;

        #pragma unroll
        for (int kt = 0; kt < 2; kt++) {
            uint32_t aH[2][4], aL[2][4], bF[4][2];
            const uint32_t TkA = (uint32_t)(kt * 2) + (midx >> 1);
            const uint32_t TkB = (uint32_t)(kt * 2) + (midx & 1);
            // B: 2 x4-LDSMs; frag pairs (nf0,nf1) at Tn=wn*2, (nf2,nf3) at Tn=4+wn*2
            #pragma unroll
            for (int nj = 0; nj < 2; nj++) {
                uint32_t Tn = (uint32_t)(nj * 4 + wn * 2) + (midx >> 1);
                uint32_t addr = bBase + (Tn * 4 + TkB) * 128 + ((rsel ^ TkB) * 16);
                uint32_t r0, r1, r2, r3;
                LDMATRIX_X4(r0, r1, r2, r3, addr);
                bF[nj * 2][0] = r0; bF[nj * 2][1] = r1;
                bF[nj * 2 + 1][0] = r2; bF[nj * 2 + 1][1] = r3;
            }
            #pragma unroll
            for (int mi = 0; mi < 2; mi++) {
                uint32_t Tm = (uint32_t)(wm * 4 + mi * 2) + (midx & 1);
                uint32_t addr = aBaseH + (Tm * 4 + TkA) * 128 + ((rsel ^ TkA) * 16);
                LDMATRIX_X4(aH[mi][0], aH[mi][1], aH[mi][2], aH[mi][3], addr);
            }
            #pragma unroll
            for (int mi = 0; mi < 2; mi++) {
                uint32_t Tm = (uint32_t)(wm * 4 + mi * 2) + (midx & 1);
                uint32_t addr = aBaseL + (Tm * 4 + TkA) * 128 + ((rsel ^ TkA) * 16);
                LDMATRIX_X4(aL[mi][0], aL[mi][1], aL[mi][2], aL[mi][3], addr);
            }
            #pragma unroll
            for (int mi = 0; mi < 2; mi++)
                #pragma unroll
                for (int nf = 0; nf < 4; nf++)
                    MMA_F16(acc[mi][nf], aH[mi], bF[nf]);
            #pragma unroll
            for (int mi = 0; mi < 2; mi++)
                #pragma unroll
                for (int nf = 0; nf < 4; nf++)
                    MMA_F16(acc[mi][nf], aL[mi], bF[nf]);
        }
        __syncthreads();
    }

    // column map within the 64-wide tile
    auto colmap = [&](int nf) { return wn * 16 + (nf & 1) * 8 + (nf >> 1) * 32; };

    if (!QKV) {
        #pragma unroll
        for (int mi = 0; mi < 2; mi++) {
            int row = m0 + wm * 32 + mi * 16 + (lane >> 2);
            #pragma unroll
            for (int nf = 0; nf < 4; nf++) {
                int col = n0 + colmap(nf) + (lane & 3) * 2;
                float b0 = bias[col], b1 = bias[col + 1];
                float2 v0, v1;
                v0.x = acc[mi][nf][0] + b0; v0.y = acc[mi][nf][1] + b1;
                v1.x = acc[mi][nf][2] + b0; v1.y = acc[mi][nf][3] + b1;
                *(float2*)&Cout[(size_t)row * DMODEL + col] = v0;
                *(float2*)&Cout[(size_t)(row + 8) * DMODEL + col] = v1;
            }
        }
        return;
    }

    // rope: pairs (nf, nf+2) = (c, c+32), c = wn*16 + nf*8 + (lane&3)*2 < 32
    if (do_rope) {
        #pragma unroll
        for (int mi = 0; mi < 2; mi++) {
            int r0 = m0 + wm * 32 + mi * 16 + (lane >> 2);
            int pos0 = r0 & (L_SEQ - 1);
            int pos1 = (r0 + 8) & (L_SEQ - 1);
            #pragma unroll
            for (int nf = 0; nf < 2; nf++) {
                int c = wn * 16 + nf * 8 + (lane & 3) * 2;
                float2 csA0 = *(float2*)&g_cs[pos0 * 64 + c * 2];
                float2 csB0 = *(float2*)&g_cs[pos0 * 64 + c * 2 + 2];
                float2 csA1 = *(float2*)&g_cs[pos1 * 64 + c * 2];
                float2 csB1 = *(float2*)&g_cs[pos1 * 64 + c * 2 + 2];
                float x1, x2;
                x1 = acc[mi][nf][0]; x2 = acc[mi][nf + 2][0];
                acc[mi][nf][0]     = x1 * csA0.x - x2 * csA0.y;
                acc[mi][nf + 2][0] = x1 * csA0.y + x2 * csA0.x;
                x1 = acc[mi][nf][1]; x2 = acc[mi][nf + 2][1];
                acc[mi][nf][1]     = x1 * csB0.x - x2 * csB0.y;
                acc[mi][nf + 2][1] = x1 * csB0.y + x2 * csB0.x;
                x1 = acc[mi][nf][2]; x2 = acc[mi][nf + 2][2];
                acc[mi][nf][2]     = x1 * csA1.x - x2 * csA1.y;
                acc[mi][nf + 2][2] = x1 * csA1.y + x2 * csA1.x;
                x1 = acc[mi][nf][3]; x2 = acc[mi][nf + 2][3];
                acc[mi][nf][3]     = x1 * csB1.x - x2 * csB1.y;
                acc[mi][nf + 2][3] = x1 * csB1.y + x2 * csB1.x;
            }
        }
    }

    if (do_scale) {
        const float sc = 0.08838834764831845f;
        #pragma unroll
        for (int mi = 0; mi < 2; mi++)
            #pragma unroll
            for (int nf = 0; nf < 4; nf++)
                #pragma unroll
                for (int c = 0; c < 4; c++) acc[mi][nf][c] *= sc;
    }

    #pragma unroll
    for (int mi = 0; mi < 2; mi++) {
        int row = m0 + wm * 32 + mi * 16 + (lane >> 2);
        #pragma unroll
        for (int nf = 0; nf < 4; nf++) {
            int cl = colBase + colmap(nf) + (lane & 3) * 2;
            uint32_t lo, hi;
            hi = pack_split(acc[mi][nf][0], acc[mi][nf][1], lo);
            *(uint32_t*)&OutH[(size_t)row * strideO + cl] = hi;
            if (OutL) *(uint32_t*)&OutL[(size_t)row * strideO + cl] = lo;
            hi = pack_split(acc[mi][nf][2], acc[mi][nf][3], lo);
            *(uint32_t*)&OutH[(size_t)(row + 8) * strideO + cl] = hi;
            if (OutL) *(uint32_t*)&OutL[(size_t)(row + 8) * strideO + cl] = lo;
        }
    }
}

// ======== attention: 64-row Q tiles, 128 threads, 3-stage KV, 2 CTAs/SM ========
__global__ void __launch_bounds__(128, 2)
attn_mma_kernel(const h16* __restrict__ Qh, const h16* __restrict__ Ql,
                const h16* __restrict__ Kh, const h16* __restrict__ Vh,
                h16* __restrict__ Oh, h16* __restrict__ Ol) {
    extern __shared__ char smem[];
    const uint32_t smb = smem_u32(smem);
    const uint32_t STG = 32768;
    const int tid = threadIdx.x, wid = tid >> 5, lane = tid & 31;
    const uint32_t midx = lane >> 3, rsel = lane & 7;
    const int qt = blockIdx.x, h = blockIdx.y, b = blockIdx.z;
    const int q0 = qt * 64;
    const size_t qrow0 = (size_t)(b * L_SEQ + q0);

    {
        const h16* srcQ[2] = {
            Qh + qrow0 * DMODEL + h * HDIM, Ql + qrow0 * DMODEL + h * HDIM };
        #pragma unroll
        for (int m = 0; m < 2; m++) {
            uint32_t base = smb + m * STG;
            #pragma unroll
            for (int i = 0; i < 8; i++) {
                int cid = tid + i * 128;
                int r = cid >> 4, j = cid & 15;
                uint32_t off = ((uint32_t)(r >> 3) * 16 + j) * 128
                             + ((uint32_t)((r & 7) ^ (j & 7)) * 16);
                CP_ASYNC16(base + off, srcQ[m] + (size_t)r * DMODEL + j * 8);
            }
        }
        CP_COMMIT();
        CP_WAIT0();
        __syncthreads();
    }
    uint32_t qHf[8][4], qLf[8][4];
    {
        const uint32_t TmA = (uint32_t)(wid * 2) + (midx & 1);
        #pragma unroll
        for (int ks = 0; ks < 8; ks++) {
            uint32_t TkA = (uint32_t)(ks * 2) + (midx >> 1);
            uint32_t offA = (TmA * 16 + TkA) * 128 + ((rsel ^ (TkA & 7)) * 16);
            LDMATRIX_X4(qHf[ks][0], qHf[ks][1], qHf[ks][2], qHf[ks][3], smb + offA);
            LDMATRIX_X4(qLf[ks][0], qLf[ks][1], qLf[ks][2], qLf[ks][3], smb + STG + offA);
        }
    }
    __syncthreads();

    int t0 = q0 - (WINDOW - 1);
    if (t0 < 0) t0 = 0;
    t0 >>= 6;
    const int t1 = qt;
    const int tmask_lo = qt - 8;

    auto fill_kv = [&](int t) {
        const uint32_t sb = smb + (uint32_t)((t - t0) % 3) * STG;
        const size_t rowb = (size_t)(b * L_SEQ + t * 64);
        const h16* srcs[2] = { Kh + rowb * HDIM, Vh + rowb * HDIM };
        #pragma unroll
        for (int m = 0; m < 2; m++) {
            uint32_t base = sb + m * 16384;
            #pragma unroll
            for (int i = 0; i < 8; i++) {
                int cid = tid + i * 128;
                int r = cid >> 4, j = cid & 15;
                uint32_t off;
                if (m == 0)
                    off = ((uint32_t)(r >> 3) * 16 + j) * 128
                        + ((uint32_t)((r & 7) ^ (j & 7)) * 16);
                else
                    off = (uint32_t)r * 256 + ((uint32_t)(j ^ (r & 7)) * 16);
                CP_ASYNC16(base + off, srcs[m] + (size_t)r * HDIM + j * 8);
            }
        }
    };

    fill_kv(t0); CP_COMMIT();
    if (t0 + 1 <= t1) { fill_kv(t0 + 1); CP_COMMIT(); }

    float acc[16][4];
    #pragma unroll
    for (int i = 0; i < 16; i++)
        #pragma unroll
        for (int c = 0; c < 4; c++) acc[i][c] = 0.0f;
    float m0r = -1e30f, m1r = -1e30f, l0r = 0.0f, l1r = 0.0f;

    const int gR0 = q0 + wid * 16 + (lane >> 2);

    for (int t = t0; t <= t1; t++) {
        if (t + 2 <= t1) { fill_kv(t + 2); CP_COMMIT(); }
        int rem = t1 - t;
        if (rem >= 2) CP_WAIT2();
        else if (rem == 1) CP_WAIT1();
        else CP_WAIT0();
        __syncthreads();

        const uint32_t sKV = smb + (uint32_t)((t - t0) % 3) * STG;
        const uint32_t sKh = sKV;
        const uint32_t sVh = sKV + 16384;
        const int kbase = t * 64;

        float sc[8][4];
        #pragma unroll
        for (int i = 0; i < 8; i++)
            #pragma unroll
            for (int c = 0; c < 4; c++) sc[i][c] = 0.0f;

        #pragma unroll
        for (int ks = 0; ks < 8; ks++) {
            uint32_t bH[8][2];
            uint32_t TkB = (uint32_t)(ks * 2) + (midx & 1);
            #pragma unroll
            for (int nj = 0; nj < 4; nj++) {
                uint32_t Tn = (uint32_t)(nj * 2) + (midx >> 1);
                uint32_t off = (Tn * 16 + TkB) * 128 + ((rsel ^ (TkB & 7)) * 16);
                uint32_t r0, r1, r2, r3;
                LDMATRIX_X4(r0, r1, r2, r3, sKh + off);
                bH[nj * 2][0] = r0; bH[nj * 2][1] = r1;
                bH[nj * 2 + 1][0] = r2; bH[nj * 2 + 1][1] = r3;
            }
            #pragma unroll
            for (int nf = 0; nf < 8; nf++) MMA_F16(sc[nf], qHf[ks], bH[nf]);
            #pragma unroll
            for (int nf = 0; nf < 8; nf++) MMA_F16(sc[nf], qLf[ks], bH[nf]);
        }

        if (t == t1 || t == tmask_lo) {
            #pragma unroll
            for (int nf = 0; nf < 8; nf++) {
                int col = kbase + nf * 8 + (lane & 3) * 2;
                int d00 = gR0 - col, d01 = d00 - 1;
                int d10 = gR0 + 8 - col, d11 = d10 - 1;
                sc[nf][0] += (d00 >= 0 && d00 < WINDOW) ? 0.f : -1e9f;
                sc[nf][1] += (d01 >= 0 && d01 < WINDOW) ? 0.f : -1e9f;
                sc[nf][2] += (d10 >= 0 && d10 < WINDOW) ? 0.f : -1e9f;
                sc[nf][3] += (d11 >= 0 && d11 < WINDOW) ? 0.f : -1e9f;
            }
        }

        float mx0 = -1e30f, mx1 = -1e30f;
        #pragma unroll
        for (int nf = 0; nf < 8; nf++) {
            mx0 = fmaxf(mx0, fmaxf(sc[nf][0], sc[nf][1]));
            mx1 = fmaxf(mx1, fmaxf(sc[nf][2], sc[nf][3]));
        }
        mx0 = fmaxf(mx0, __shfl_xor_sync(0xffffffffu, mx0, 1));
        mx0 = fmaxf(mx0, __shfl_xor_sync(0xffffffffu, mx0, 2));
        mx1 = fmaxf(mx1, __shfl_xor_sync(0xffffffffu, mx1, 1));
        mx1 = fmaxf(mx1, __shfl_xor_sync(0xffffffffu, mx1, 2));
        float mn0 = fmaxf(m0r, mx0), mn1 = fmaxf(m1r, mx1);
        float corr0 = __expf(m0r - mn0), corr1 = __expf(m1r - mn1);
        m0r = mn0; m1r = mn1;
        float rs0 = 0.f, rs1 = 0.f;
        #pragma unroll
        for (int nf = 0; nf < 8; nf++) {
            sc[nf][0] = __expf(sc[nf][0] - mn0);
            sc[nf][1] = __expf(sc[nf][1] - mn0);
            sc[nf][2] = __expf(sc[nf][2] - mn1);
            sc[nf][3] = __expf(sc[nf][3] - mn1);
            rs0 += sc[nf][0] + sc[nf][1];
            rs1 += sc[nf][2] + sc[nf][3];
        }
        rs0 += __shfl_xor_sync(0xffffffffu, rs0, 1);
        rs0 += __shfl_xor_sync(0xffffffffu, rs0, 2);
        rs1 += __shfl_xor_sync(0xffffffffu, rs1, 1);
        rs1 += __shfl_xor_sync(0xffffffffu, rs1, 2);
        l0r = l0r * corr0 + rs0;
        l1r = l1r * corr1 + rs1;
        #pragma unroll
        for (int nf = 0; nf < 16; nf++) {
            acc[nf][0] *= corr0; acc[nf][1] *= corr0;
            acc[nf][2] *= corr1; acc[nf][3] *= corr1;
        }

        uint32_t aPh[4][4], aPl[4][4];
        #pragma unroll
        for (int kt2 = 0; kt2 < 4; kt2++) {
            #pragma unroll
            for (int half = 0; half < 2; half++) {
                int nf = kt2 * 2 + half;
                uint32_t lo01, lo23;
                uint32_t hi01 = pack_split(sc[nf][0], sc[nf][1], lo01);
                uint32_t hi23 = pack_split(sc[nf][2], sc[nf][3], lo23);
                aPh[kt2][half * 2 + 0] = hi01;
                aPh[kt2][half * 2 + 1] = hi23;
                aPl[kt2][half * 2 + 0] = lo01;
                aPl[kt2][half * 2 + 1] = lo23;
            }
        }

        #pragma unroll
        for (int kt2 = 0; kt2 < 4; kt2++) {
            uint32_t bb[16][2];
            uint32_t krow = (uint32_t)(kt2 * 16) + ((midx & 1) * 8) + rsel;
            #pragma unroll
            for (int nj = 0; nj < 8; nj++) {
                uint32_t j = (uint32_t)(nj * 2) + (midx >> 1);
                uint32_t off = krow * 256 + ((j ^ rsel) * 16);
                uint32_t r0, r1, r2, r3;
                LDMATRIX_X4_T(r0, r1, r2, r3, sVh + off);
                bb[nj * 2][0] = r0; bb[nj * 2][1] = r1;
                bb[nj * 2 + 1][0] = r2; bb[nj * 2 + 1][1] = r3;
            }
            #pragma unroll
            for (int nf = 0; nf < 16; nf++) MMA_F16(acc[nf], aPh[kt2], bb[nf]);
            #pragma unroll
            for (int nf = 0; nf < 16; nf++) MMA_F16(acc[nf], aPl[kt2], bb[nf]);
        }
        __syncthreads();
    }

    float inv0 = 1.0f / l0r, inv1 = 1.0f / l1r;
    size_t row0 = qrow0 + wid * 16 + (lane >> 2);
    size_t row1 = row0 + 8;
    #pragma unroll
    for (int nf = 0; nf < 16; nf++) {
        int col = h * HDIM + nf * 8 + (lane & 3) * 2;
        uint32_t lo, hi;
        hi = pack_split(acc[nf][0] * inv0, acc[nf][1] * inv0, lo);
        *(uint32_t*)&Oh[row0 * DMODEL + col] = hi;
        *(uint32_t*)&Ol[row0 * DMODEL + col] = lo;
        hi = pack_split(acc[nf][2] * inv1, acc[nf][3] * inv1, lo);
        *(uint32_t*)&Oh[row1 * DMODEL + col] = hi;
        *(uint32_t*)&Ol[row1 * DMODEL + col] = lo;
    }
}

// ================= launch =================
extern "C" void kernel_launch(void* const* d_in, const int* in_sizes, int n_in,
                              void* d_out, int out_size) {
    const float* x  = (const float*)d_in[0];
    const float* Wq = (const float*)d_in[1];
    const float* Wk = (const float*)d_in[2];
    const float* Wv = (const float*)d_in[3];
    const float* Wo = (const float*)d_in[4];
    const float* bo = (const float*)d_in[5];
    float* out = (float*)d_out;

    h16 *qh, *ql, *kh, *vh, *ath, *atl, *wqh, *woh;
    cudaGetSymbolAddress((void**)&qh,  g_qh);
    cudaGetSymbolAddress((void**)&ql,  g_ql);
    cudaGetSymbolAddress((void**)&kh,  g_kh);
    cudaGetSymbolAddress((void**)&vh,  g_vh);
    cudaGetSymbolAddress((void**)&ath, g_ath);
    cudaGetSymbolAddress((void**)&atl, g_atl);
    cudaGetSymbolAddress((void**)&wqh, g_wqt_h);
    cudaGetSymbolAddress((void**)&woh, g_wot_h);

    const int GEMM_SMEM = 61440;    // 3 stages x 20KB
    cudaFuncSetAttribute(gemm_kernel<true>,
                         cudaFuncAttributeMaxDynamicSharedMemorySize, GEMM_SMEM);
    cudaFuncSetAttribute(gemm_kernel<false>,
                         cudaFuncAttributeMaxDynamicSharedMemorySize, GEMM_SMEM);
    const int ATTN_SMEM = 98304;    // 3 KV stages x 32KB
    cudaFuncSetAttribute(attn_mma_kernel,
                         cudaFuncAttributeMaxDynamicSharedMemorySize, ATTN_SMEM);

    dim3 tb(32, 8);
    // launch 0: rope table + x split (combined)
    prep_kernel<<<(BROWS * DMODEL) / 256, 256>>>(x, BROWS * DMODEL);
    // launches 1,2: weights needed by QKV gemm
    thalf_kernel<<<dim3(DMODEL / 32, KDIM / 32), tb>>>(Wq, wqh, DMODEL, 0);
    thalf_kv_kernel<<<dim3(HDIM / 32, KDIM / 32, 2), tb>>>(Wk, Wv);
    // launch 3: fused QKV projection + RoPE + scale + split  (ncu capture slot)
    gemm_kernel<true><<<dim3(36, BROWS / 128), 256, GEMM_SMEM>>>(nullptr, nullptr);
    // launch 4: Wo transpose (independent of attention)
    thalf_kernel<<<dim3(DMODEL / 32, KDIM / 32), tb>>>(Wo, woh, DMODEL, 0);
    // launch 5: attention
    dim3 ga(L_SEQ / 64, NHEADS, 2);
    attn_mma_kernel<<<ga, 128, ATTN_SMEM>>>(qh, ql, kh, vh, ath, atl);
    // launch 6: output projection + bias
    gemm_kernel<false><<<dim3(32, BROWS / 128), 256, GEMM_SMEM>>>(bo, out);
}

// round 16
// speedup vs baseline: 1.1223x; 1.1223x over previous
#include <cuda_runtime.h>
#include <cuda_fp16.h>
#include <math.h>
#include <stdint.h>

#define L_SEQ   2048
#define DMODEL  2048
#define NHEADS  16
#define HDIM    128
#define WINDOW  512
#define BROWS   4096   // B * L
#define KDIM    2048

typedef __half h16;

// ================= scratch =================
__device__ float g_cs[L_SEQ * 64];          // (cos,sin) interleaved
__device__ h16 g_xh[BROWS * DMODEL];
__device__ h16 g_xl[BROWS * DMODEL];        // scaled x1024 (GEMM lo-pass only)
__device__ h16 g_qh[BROWS * DMODEL];
__device__ h16 g_ql[BROWS * DMODEL];        // unscaled (attention)
__device__ h16 g_kh[BROWS * HDIM];
__device__ h16 g_vh[BROWS * HDIM];
__device__ h16 g_ath[BROWS * DMODEL];
__device__ h16 g_atl[BROWS * DMODEL];       // scaled x1024 (GEMM lo-pass only)
__device__ h16 g_wqt_h[DMODEL * KDIM];
__device__ h16 g_wot_h[DMODEL * KDIM];
__device__ h16 g_wkvt_h[256 * KDIM];

// ================= helpers =================
__device__ __forceinline__ uint32_t smem_u32(const void* p) {
    uint32_t a;
    asm("{ .reg .u64 t; cvta.to.shared.u64 t, %1; cvt.u32.u64 %0, t; }" : "=r"(a) : "l"(p));
    return a;
}
#define CP_ASYNC16(saddr, gptr) \
    asm volatile("cp.async.cg.shared.global [%0], [%1], 16;" :: "r"(saddr), "l"(gptr))
#define CP_COMMIT()  asm volatile("cp.async.commit_group;" ::: "memory")
#define CP_WAIT0()   asm volatile("cp.async.wait_group 0;" ::: "memory")
#define CP_WAIT1()   asm volatile("cp.async.wait_group 1;" ::: "memory")
#define CP_WAIT2()   asm volatile("cp.async.wait_group 2;" ::: "memory")

#define LDMATRIX_X4(r0, r1, r2, r3, addr) \
    asm volatile("ldmatrix.sync.aligned.m8n8.x4.shared.b16 {%0,%1,%2,%3}, [%4];" \
        : "=r"(r0), "=r"(r1), "=r"(r2), "=r"(r3) : "r"(addr))

#define LDMATRIX_X4_T(r0, r1, r2, r3, addr) \
    asm volatile("ldmatrix.sync.aligned.m8n8.x4.trans.shared.b16 {%0,%1,%2,%3}, [%4];" \
        : "=r"(r0), "=r"(r1), "=r"(r2), "=r"(r3) : "r"(addr))

#define MMA_F16(c, a, b) \
    asm volatile("mma.sync.aligned.m16n8k16.row.col.f32.f16.f16.f32 " \
        "{%0,%1,%2,%3}, {%4,%5,%6,%7}, {%8,%9}, {%0,%1,%2,%3};" \
        : "+f"((c)[0]), "+f"((c)[1]), "+f"((c)[2]), "+f"((c)[3]) \
        : "r"((a)[0]), "r"((a)[1]), "r"((a)[2]), "r"((a)[3]), "r"((b)[0]), "r"((b)[1]))

// fp16-accumulator MMA (lo-pass): D,C are 2 regs of half2
#define MMA_F16ACC(c, a, b) \
    asm volatile("mma.sync.aligned.m16n8k16.row.col.f16.f16.f16.f16 " \
        "{%0,%1}, {%2,%3,%4,%5}, {%6,%7}, {%0,%1};" \
        : "+r"((c)[0]), "+r"((c)[1]) \
        : "r"((a)[0]), "r"((a)[1]), "r"((a)[2]), "r"((a)[3]), "r"((b)[0]), "r"((b)[1]))

__device__ __forceinline__ uint32_t pack_split(float a, float b, uint32_t& lo) {
    __half2 h = __floats2half2_rn(a, b);
    __half2 l = __floats2half2_rn(a - __low2float(h), b - __high2float(h));
    lo = *(uint32_t*)&l;
    return *(uint32_t*)&h;
}
__device__ __forceinline__ uint32_t pack_split_s(float a, float b, uint32_t& lo, float s) {
    __half2 h = __floats2half2_rn(a, b);
    __half2 l = __floats2half2_rn((a - __low2float(h)) * s, (b - __high2float(h)) * s);
    lo = *(uint32_t*)&l;
    return *(uint32_t*)&h;
}

// ================= prep kernels =================
__global__ void prep_kernel(const float* __restrict__ in, int n) {
    int idx = blockIdx.x * blockDim.x + threadIdx.x;
    if (idx < L_SEQ * 32) {
        int pos = idx >> 5;
        int i = idx & 31;
        double inv = exp(-log(10000.0) * ((double)(2 * i) / 64.0));
        double th = (double)pos * inv;
        g_cs[pos * 64 + i * 2 + 0] = (float)cos(th);
        g_cs[pos * 64 + i * 2 + 1] = (float)sin(th);
    }
    if (idx < n) {
        float v = in[idx];
        h16 h = __float2half_rn(v);
        g_xh[idx] = h;
        g_xl[idx] = __float2half_rn((v - __half2float(h)) * 1024.0f);
    }
}

__global__ void thalf_kernel(const float* __restrict__ W,
                             h16* __restrict__ Th, int N, int ro) {
    __shared__ float tile[32][33];
    int n0 = blockIdx.x * 32, k0 = blockIdx.y * 32;
    int tx = threadIdx.x, ty = threadIdx.y;
    #pragma unroll
    for (int i = ty; i < 32; i += 8)
        tile[i][tx] = W[(size_t)(k0 + i) * N + n0 + tx];
    __syncthreads();
    #pragma unroll
    for (int i = ty; i < 32; i += 8)
        Th[(size_t)(ro + n0 + i) * KDIM + k0 + tx] = __float2half_rn(tile[tx][i]);
}

__global__ void thalf_kv_kernel(const float* __restrict__ Wk,
                                const float* __restrict__ Wv) {
    __shared__ float tile[32][33];
    const float* W = blockIdx.z ? Wv : Wk;
    int ro = blockIdx.z ? 128 : 0;
    int n0 = blockIdx.x * 32, k0 = blockIdx.y * 32;
    int tx = threadIdx.x, ty = threadIdx.y;
    #pragma unroll
    for (int i = ty; i < 32; i += 8)
        tile[i][tx] = W[(size_t)(k0 + i) * HDIM + n0 + tx];
    __syncthreads();
    #pragma unroll
    for (int i = ty; i < 32; i += 8)
        g_wkvt_h[(size_t)(ro + n0 + i) * KDIM + k0 + tx] = __float2half_rn(tile[tx][i]);
}

// ===== mma.sync fp16 2-pass GEMM, K32, 3-stage; lo-pass in fp16 accum =====
// per stage: A-hi 8KB + A-lo 8KB + B 8KB = 24KB; 3 stages = 72KB; 2 CTAs/SM.
template <bool QKV>
__global__ void __launch_bounds__(256, 2)
gemm_kernel(const float* __restrict__ bias, float* __restrict__ Cout) {
    extern __shared__ char smem[];
    const uint32_t smb = smem_u32(smem);
    const int tid = threadIdx.x;
    const int wid = tid >> 5;
    const int lane = tid & 31;
    const int wm = wid >> 1;
    const int wn = wid & 1;
    const uint32_t midx = lane >> 3;
    const uint32_t rsel = lane & 7;

    const int m0 = blockIdx.y * 128;
    const h16* Ah = QKV ? g_xh : g_ath;
    const h16* Al = QKV ? g_xl : g_atl;
    const h16* Bh;
    int n0;
    h16 *OutH = nullptr, *OutL = nullptr;
    int strideO = 0, colBase = 0;
    bool do_rope = false, do_scale = false;
    if (QKV) {
        if ((int)blockIdx.x < 16) {
            Bh = g_wqt_h; n0 = blockIdx.x * 128;
            OutH = g_qh; OutL = g_ql; strideO = DMODEL; colBase = n0;
            do_rope = true; do_scale = true;
        } else if (blockIdx.x == 16) {
            Bh = g_wkvt_h; n0 = 0;
            OutH = g_kh; OutL = nullptr; strideO = HDIM; colBase = 0; do_rope = true;
        } else {
            Bh = g_wkvt_h; n0 = 128;
            OutH = g_vh; OutL = nullptr; strideO = HDIM; colBase = 0; do_rope = false;
        }
    } else {
        Bh = g_wot_h; n0 = blockIdx.x * 128;
    }

    const h16* srcs[3] = {
        Ah + (size_t)m0 * KDIM, Al + (size_t)m0 * KDIM, Bh + (size_t)n0 * KDIM };

    const int fr = tid >> 2;
    const uint32_t fkt = (uint32_t)(tid & 3);
    const int fc0 = (tid & 3) * 8;

    auto fill = [&](int kc, uint32_t sbase) {
        #pragma unroll
        for (int m = 0; m < 3; m++)
            #pragma unroll
            for (int half = 0; half < 2; half++) {
                int rr = fr + half * 64;
                uint32_t off = ((uint32_t)(rr >> 3) * 4 + fkt) * 128
                             + ((uint32_t)((rr & 7) ^ fkt) * 16);
                CP_ASYNC16(sbase + m * 8192 + off,
                           srcs[m] + (size_t)rr * KDIM + kc * 32 + fc0);
            }
    };

    float acc[2][8][4];
    uint32_t accLo[2][8][2];
    #pragma unroll
    for (int i = 0; i < 2; i++)
        #pragma unroll
        for (int j = 0; j < 8; j++) {
            #pragma unroll
            for (int c = 0; c < 4; c++) acc[i][j][c] = 0.0f;
            accLo[i][j][0] = 0u; accLo[i][j][1] = 0u;
        }

    fill(0, smb);          CP_COMMIT();
    fill(1, smb + 24576);  CP_COMMIT();

    const int NK = KDIM / 32;
    for (int kc = 0; kc < NK; kc++) {
        if (kc + 1 < NK) CP_WAIT1(); else CP_WAIT0();
        __syncthreads();
        if (kc + 2 < NK) {
            fill(kc + 2, smb + ((kc + 2) % 3) * 24576);
            CP_COMMIT();
        }

        const uint32_t sb = smb + (kc % 3) * 24576;
        const uint32_t aBaseH = sb;
        const uint32_t aBaseL = sb + 8192;
        const uint32_t bBaseH = sb + 16384;

        #pragma unroll
        for (int kt = 0; kt < 2; kt++) {
            uint32_t aF[2][4], bF[8][2];
            const uint32_t TkA = (uint32_t)(kt * 2) + (midx >> 1);
            const uint32_t TkB = (uint32_t)(kt * 2) + (midx & 1);
            #pragma unroll
            for (int nj = 0; nj < 4; nj++) {
                uint32_t Tn = (uint32_t)(wn * 8 + nj * 2) + (midx >> 1);
                uint32_t addr = bBaseH + (Tn * 4 + TkB) * 128 + ((rsel ^ TkB) * 16);
                uint32_t r0, r1, r2, r3;
                LDMATRIX_X4(r0, r1, r2, r3, addr);
                bF[nj * 2][0] = r0; bF[nj * 2][1] = r1;
                bF[nj * 2 + 1][0] = r2; bF[nj * 2 + 1][1] = r3;
            }
            // hi pass (fp32 accum)
            #pragma unroll
            for (int mi = 0; mi < 2; mi++) {
                uint32_t Tm = (uint32_t)(wm * 4 + mi * 2) + (midx & 1);
                uint32_t addr = aBaseH + (Tm * 4 + TkA) * 128 + ((rsel ^ TkA) * 16);
                LDMATRIX_X4(aF[mi][0], aF[mi][1], aF[mi][2], aF[mi][3], addr);
            }
            #pragma unroll
            for (int mi = 0; mi < 2; mi++)
                #pragma unroll
                for (int nf = 0; nf < 8; nf++)
                    MMA_F16(acc[mi][nf], aF[mi], bF[nf]);
            // lo pass (fp16 accum, operands pre-scaled x1024)
            #pragma unroll
            for (int mi = 0; mi < 2; mi++) {
                uint32_t Tm = (uint32_t)(wm * 4 + mi * 2) + (midx & 1);
                uint32_t addr = aBaseL + (Tm * 4 + TkA) * 128 + ((rsel ^ TkA) * 16);
                LDMATRIX_X4(aF[mi][0], aF[mi][1], aF[mi][2], aF[mi][3], addr);
            }
            #pragma unroll
            for (int mi = 0; mi < 2; mi++)
                #pragma unroll
                for (int nf = 0; nf < 8; nf++)
                    MMA_F16ACC(accLo[mi][nf], aF[mi], bF[nf]);
        }
        __syncthreads();
    }

    // merge lo (scaled back by 1/1024)
    const float INVS = 0.0009765625f;
    #pragma unroll
    for (int mi = 0; mi < 2; mi++)
        #pragma unroll
        for (int nf = 0; nf < 8; nf++) {
            float2 f01 = __half22float2(*(__half2*)&accLo[mi][nf][0]);
            float2 f23 = __half22float2(*(__half2*)&accLo[mi][nf][1]);
            acc[mi][nf][0] += f01.x * INVS;
            acc[mi][nf][1] += f01.y * INVS;
            acc[mi][nf][2] += f23.x * INVS;
            acc[mi][nf][3] += f23.y * INVS;
        }

    if (!QKV) {
        #pragma unroll
        for (int mi = 0; mi < 2; mi++) {
            int row = m0 + wm * 32 + mi * 16 + (lane >> 2);
            #pragma unroll
            for (int nf = 0; nf < 8; nf++) {
                int col = n0 + wn * 64 + nf * 8 + (lane & 3) * 2;
                float b0 = bias[col], b1 = bias[col + 1];
                float2 v0, v1;
                v0.x = acc[mi][nf][0] + b0; v0.y = acc[mi][nf][1] + b1;
                v1.x = acc[mi][nf][2] + b0; v1.y = acc[mi][nf][3] + b1;
                *(float2*)&Cout[(size_t)row * DMODEL + col] = v0;
                *(float2*)&Cout[(size_t)(row + 8) * DMODEL + col] = v1;
            }
        }
        return;
    }

    if (do_rope && wn == 0) {
        #pragma unroll
        for (int mi = 0; mi < 2; mi++) {
            int r0 = m0 + wm * 32 + mi * 16 + (lane >> 2);
            int pos0 = r0 & (L_SEQ - 1);
            int pos1 = (r0 + 8) & (L_SEQ - 1);
            #pragma unroll
            for (int nf = 0; nf < 4; nf++) {
                int c = nf * 8 + (lane & 3) * 2;
                float2 csA0 = *(float2*)&g_cs[pos0 * 64 + c * 2];
                float2 csB0 = *(float2*)&g_cs[pos0 * 64 + c * 2 + 2];
                float2 csA1 = *(float2*)&g_cs[pos1 * 64 + c * 2];
                float2 csB1 = *(float2*)&g_cs[pos1 * 64 + c * 2 + 2];
                float x1, x2;
                x1 = acc[mi][nf][0]; x2 = acc[mi][nf + 4][0];
                acc[mi][nf][0]     = x1 * csA0.x - x2 * csA0.y;
                acc[mi][nf + 4][0] = x1 * csA0.y + x2 * csA0.x;
                x1 = acc[mi][nf][1]; x2 = acc[mi][nf + 4][1];
                acc[mi][nf][1]     = x1 * csB0.x - x2 * csB0.y;
                acc[mi][nf + 4][1] = x1 * csB0.y + x2 * csB0.x;
                x1 = acc[mi][nf][2]; x2 = acc[mi][nf + 4][2];
                acc[mi][nf][2]     = x1 * csA1.x - x2 * csA1.y;
                acc[mi][nf + 4][2] = x1 * csA1.y + x2 * csA1.x;
                x1 = acc[mi][nf][3]; x2 = acc[mi][nf + 4][3];
                acc[mi][nf][3]     = x1 * csB1.x - x2 * csB1.y;
                acc[mi][nf + 4][3] = x1 * csB1.y + x2 * csB1.x;
            }
        }
    }

    if (do_scale) {
        const float sc = 0.08838834764831845f;
        #pragma unroll
        for (int mi = 0; mi < 2; mi++)
            #pragma unroll
            for (int nf = 0; nf < 8; nf++)
                #pragma unroll
                for (int c = 0; c < 4; c++) acc[mi][nf][c] *= sc;
    }

    #pragma unroll
    for (int mi = 0; mi < 2; mi++) {
        int row = m0 + wm * 32 + mi * 16 + (lane >> 2);
        #pragma unroll
        for (int nf = 0; nf < 8; nf++) {
            int cl = colBase + wn * 64 + nf * 8 + (lane & 3) * 2;
            uint32_t lo, hi;
            hi = pack_split(acc[mi][nf][0], acc[mi][nf][1], lo);
            *(uint32_t*)&OutH[(size_t)row * strideO + cl] = hi;
            if (OutL) *(uint32_t*)&OutL[(size_t)row * strideO + cl] = lo;
            hi = pack_split(acc[mi][nf][2], acc[mi][nf][3], lo);
            *(uint32_t*)&OutH[(size_t)(row + 8) * strideO + cl] = hi;
            if (OutL) *(uint32_t*)&OutL[(size_t)(row + 8) * strideO + cl] = lo;
        }
    }
}

// ======== attention: 64-row Q tiles, 128 threads, 3-stage KV, 2 CTAs/SM ========
__global__ void __launch_bounds__(128, 2)
attn_mma_kernel(const h16* __restrict__ Qh, const h16* __restrict__ Ql,
                const h16* __restrict__ Kh, const h16* __restrict__ Vh,
                h16* __restrict__ Oh, h16* __restrict__ Ol) {
    extern __shared__ char smem[];
    const uint32_t smb = smem_u32(smem);
    const uint32_t STG = 32768;
    const int tid = threadIdx.x, wid = tid >> 5, lane = tid & 31;
    const uint32_t midx = lane >> 3, rsel = lane & 7;
    const int qt = blockIdx.x, h = blockIdx.y, b = blockIdx.z;
    const int q0 = qt * 64;
    const size_t qrow0 = (size_t)(b * L_SEQ + q0);

    {
        const h16* srcQ[2] = {
            Qh + qrow0 * DMODEL + h * HDIM, Ql + qrow0 * DMODEL + h * HDIM };
        #pragma unroll
        for (int m = 0; m < 2; m++) {
            uint32_t base = smb + m * STG;
            #pragma unroll
            for (int i = 0; i < 8; i++) {
                int cid = tid + i * 128;
                int r = cid >> 4, j = cid & 15;
                uint32_t off = ((uint32_t)(r >> 3) * 16 + j) * 128
                             + ((uint32_t)((r & 7) ^ (j & 7)) * 16);
                CP_ASYNC16(base + off, srcQ[m] + (size_t)r * DMODEL + j * 8);
            }
        }
        CP_COMMIT();
        CP_WAIT0();
        __syncthreads();
    }
    uint32_t qHf[8][4], qLf[8][4];
    {
        const uint32_t TmA = (uint32_t)(wid * 2) + (midx & 1);
        #pragma unroll
        for (int ks = 0; ks < 8; ks++) {
            uint32_t TkA = (uint32_t)(ks * 2) + (midx >> 1);
            uint32_t offA = (TmA * 16 + TkA) * 128 + ((rsel ^ (TkA & 7)) * 16);
            LDMATRIX_X4(qHf[ks][0], qHf[ks][1], qHf[ks][2], qHf[ks][3], smb + offA);
            LDMATRIX_X4(qLf[ks][0], qLf[ks][1], qLf[ks][2], qLf[ks][3], smb + STG + offA);
        }
    }
    __syncthreads();

    int t0 = q0 - (WINDOW - 1);
    if (t0 < 0) t0 = 0;
    t0 >>= 6;
    const int t1 = qt;
    const int tmask_lo = qt - 8;

    auto fill_kv = [&](int t) {
        const uint32_t sb = smb + (uint32_t)((t - t0) % 3) * STG;
        const size_t rowb = (size_t)(b * L_SEQ + t * 64);
        const h16* srcs[2] = { Kh + rowb * HDIM, Vh + rowb * HDIM };
        #pragma unroll
        for (int m = 0; m < 2; m++) {
            uint32_t base = sb + m * 16384;
            #pragma unroll
            for (int i = 0; i < 8; i++) {
                int cid = tid + i * 128;
                int r = cid >> 4, j = cid & 15;
                uint32_t off;
                if (m == 0)
                    off = ((uint32_t)(r >> 3) * 16 + j) * 128
                        + ((uint32_t)((r & 7) ^ (j & 7)) * 16);
                else
                    off = (uint32_t)r * 256 + ((uint32_t)(j ^ (r & 7)) * 16);
                CP_ASYNC16(base + off, srcs[m] + (size_t)r * HDIM + j * 8);
            }
        }
    };

    fill_kv(t0); CP_COMMIT();
    if (t0 + 1 <= t1) { fill_kv(t0 + 1); CP_COMMIT(); }

    float acc[16][4];
    #pragma unroll
    for (int i = 0; i < 16; i++)
        #pragma unroll
        for (int c = 0; c < 4; c++) acc[i][c] = 0.0f;
    float m0r = -1e30f, m1r = -1e30f, l0r = 0.0f, l1r = 0.0f;

    const int gR0 = q0 + wid * 16 + (lane >> 2);

    for (int t = t0; t <= t1; t++) {
        if (t + 2 <= t1) { fill_kv(t + 2); CP_COMMIT(); }
        int rem = t1 - t;
        if (rem >= 2) CP_WAIT2();
        else if (rem == 1) CP_WAIT1();
        else CP_WAIT0();
        __syncthreads();

        const uint32_t sKV = smb + (uint32_t)((t - t0) % 3) * STG;
        const uint32_t sKh = sKV;
        const uint32_t sVh = sKV + 16384;
        const int kbase = t * 64;

        float sc[8][4];
        #pragma unroll
        for (int i = 0; i < 8; i++)
            #pragma unroll
            for (int c = 0; c < 4; c++) sc[i][c] = 0.0f;

        #pragma unroll
        for (int ks = 0; ks < 8; ks++) {
            uint32_t bH[8][2];
            uint32_t TkB = (uint32_t)(ks * 2) + (midx & 1);
            #pragma unroll
            for (int nj = 0; nj < 4; nj++) {
                uint32_t Tn = (uint32_t)(nj * 2) + (midx >> 1);
                uint32_t off = (Tn * 16 + TkB) * 128 + ((rsel ^ (TkB & 7)) * 16);
                uint32_t r0, r1, r2, r3;
                LDMATRIX_X4(r0, r1, r2, r3, sKh + off);
                bH[nj * 2][0] = r0; bH[nj * 2][1] = r1;
                bH[nj * 2 + 1][0] = r2; bH[nj * 2 + 1][1] = r3;
            }
            #pragma unroll
            for (int nf = 0; nf < 8; nf++) MMA_F16(sc[nf], qHf[ks], bH[nf]);
            #pragma unroll
            for (int nf = 0; nf < 8; nf++) MMA_F16(sc[nf], qLf[ks], bH[nf]);
        }

        if (t == t1 || t == tmask_lo) {
            #pragma unroll
            for (int nf = 0; nf < 8; nf++) {
                int col = kbase + nf * 8 + (lane & 3) * 2;
                int d00 = gR0 - col, d01 = d00 - 1;
                int d10 = gR0 + 8 - col, d11 = d10 - 1;
                sc[nf][0] += (d00 >= 0 && d00 < WINDOW) ? 0.f : -1e9f;
                sc[nf][1] += (d01 >= 0 && d01 < WINDOW) ? 0.f : -1e9f;
                sc[nf][2] += (d10 >= 0 && d10 < WINDOW) ? 0.f : -1e9f;
                sc[nf][3] += (d11 >= 0 && d11 < WINDOW) ? 0.f : -1e9f;
            }
        }

        float mx0 = -1e30f, mx1 = -1e30f;
        #pragma unroll
        for (int nf = 0; nf < 8; nf++) {
            mx0 = fmaxf(mx0, fmaxf(sc[nf][0], sc[nf][1]));
            mx1 = fmaxf(mx1, fmaxf(sc[nf][2], sc[nf][3]));
        }
        mx0 = fmaxf(mx0, __shfl_xor_sync(0xffffffffu, mx0, 1));
        mx0 = fmaxf(mx0, __shfl_xor_sync(0xffffffffu, mx0, 2));
        mx1 = fmaxf(mx1, __shfl_xor_sync(0xffffffffu, mx1, 1));
        mx1 = fmaxf(mx1, __shfl_xor_sync(0xffffffffu, mx1, 2));
        float mn0 = fmaxf(m0r, mx0), mn1 = fmaxf(m1r, mx1);
        float corr0 = __expf(m0r - mn0), corr1 = __expf(m1r - mn1);
        m0r = mn0; m1r = mn1;
        float rs0 = 0.f, rs1 = 0.f;
        #pragma unroll
        for (int nf = 0; nf < 8; nf++) {
            sc[nf][0] = __expf(sc[nf][0] - mn0);
            sc[nf][1] = __expf(sc[nf][1] - mn0);
            sc[nf][2] = __expf(sc[nf][2] - mn1);
            sc[nf][3] = __expf(sc[nf][3] - mn1);
            rs0 += sc[nf][0] + sc[nf][1];
            rs1 += sc[nf][2] + sc[nf][3];
        }
        rs0 += __shfl_xor_sync(0xffffffffu, rs0, 1);
        rs0 += __shfl_xor_sync(0xffffffffu, rs0, 2);
        rs1 += __shfl_xor_sync(0xffffffffu, rs1, 1);
        rs1 += __shfl_xor_sync(0xffffffffu, rs1, 2);
        l0r = l0r * corr0 + rs0;
        l1r = l1r * corr1 + rs1;
        #pragma unroll
        for (int nf = 0; nf < 16; nf++) {
            acc[nf][0] *= corr0; acc[nf][1] *= corr0;
            acc[nf][2] *= corr1; acc[nf][3] *= corr1;
        }

        uint32_t aPh[4][4], aPl[4][4];
        #pragma unroll
        for (int kt2 = 0; kt2 < 4; kt2++) {
            #pragma unroll
            for (int half = 0; half < 2; half++) {
                int nf = kt2 * 2 + half;
                uint32_t lo01, lo23;
                uint32_t hi01 = pack_split(sc[nf][0], sc[nf][1], lo01);
                uint32_t hi23 = pack_split(sc[nf][2], sc[nf][3], lo23);
                aPh[kt2][half * 2 + 0] = hi01;
                aPh[kt2][half * 2 + 1] = hi23;
                aPl[kt2][half * 2 + 0] = lo01;
                aPl[kt2][half * 2 + 1] = lo23;
            }
        }

        #pragma unroll
        for (int kt2 = 0; kt2 < 4; kt2++) {
            uint32_t bb[16][2];
            uint32_t krow = (uint32_t)(kt2 * 16) + ((midx & 1) * 8) + rsel;
            #pragma unroll
            for (int nj = 0; nj < 8; nj++) {
                uint32_t j = (uint32_t)(nj * 2) + (midx >> 1);
                uint32_t off = krow * 256 + ((j ^ rsel) * 16);
                uint32_t r0, r1, r2, r3;
                LDMATRIX_X4_T(r0, r1, r2, r3, sVh + off);
                bb[nj * 2][0] = r0; bb[nj * 2][1] = r1;
                bb[nj * 2 + 1][0] = r2; bb[nj * 2 + 1][1] = r3;
            }
            #pragma unroll
            for (int nf = 0; nf < 16; nf++) MMA_F16(acc[nf], aPh[kt2], bb[nf]);
            #pragma unroll
            for (int nf = 0; nf < 16; nf++) MMA_F16(acc[nf], aPl[kt2], bb[nf]);
        }
        __syncthreads();
    }

    float inv0 = 1.0f / l0r, inv1 = 1.0f / l1r;
    size_t row0 = qrow0 + wid * 16 + (lane >> 2);
    size_t row1 = row0 + 8;
    #pragma unroll
    for (int nf = 0; nf < 16; nf++) {
        int col = h * HDIM + nf * 8 + (lane & 3) * 2;
        uint32_t lo, hi;
        hi = pack_split_s(acc[nf][0] * inv0, acc[nf][1] * inv0, lo, 1024.0f);
        *(uint32_t*)&Oh[row0 * DMODEL + col] = hi;
        *(uint32_t*)&Ol[row0 * DMODEL + col] = lo;
        hi = pack_split_s(acc[nf][2] * inv1, acc[nf][3] * inv1, lo, 1024.0f);
        *(uint32_t*)&Oh[row1 * DMODEL + col] = hi;
        *(uint32_t*)&Ol[row1 * DMODEL + col] = lo;
    }
}

// ================= launch =================
extern "C" void kernel_launch(void* const* d_in, const int* in_sizes, int n_in,
                              void* d_out, int out_size) {
    const float* x  = (const float*)d_in[0];
    const float* Wq = (const float*)d_in[1];
    const float* Wk = (const float*)d_in[2];
    const float* Wv = (const float*)d_in[3];
    const float* Wo = (const float*)d_in[4];
    const float* bo = (const float*)d_in[5];
    float* out = (float*)d_out;

    h16 *qh, *ql, *kh, *vh, *ath, *atl, *wqh, *woh;
    cudaGetSymbolAddress((void**)&qh,  g_qh);
    cudaGetSymbolAddress((void**)&ql,  g_ql);
    cudaGetSymbolAddress((void**)&kh,  g_kh);
    cudaGetSymbolAddress((void**)&vh,  g_vh);
    cudaGetSymbolAddress((void**)&ath, g_ath);
    cudaGetSymbolAddress((void**)&atl, g_atl);
    cudaGetSymbolAddress((void**)&wqh, g_wqt_h);
    cudaGetSymbolAddress((void**)&woh, g_wot_h);

    const int GEMM_SMEM = 73728;    // 3 stages x 24KB
    cudaFuncSetAttribute(gemm_kernel<true>,
                         cudaFuncAttributeMaxDynamicSharedMemorySize, GEMM_SMEM);
    cudaFuncSetAttribute(gemm_kernel<false>,
                         cudaFuncAttributeMaxDynamicSharedMemorySize, GEMM_SMEM);
    const int ATTN_SMEM = 98304;    // 3 KV stages x 32KB
    cudaFuncSetAttribute(attn_mma_kernel,
                         cudaFuncAttributeMaxDynamicSharedMemorySize, ATTN_SMEM);

    dim3 tb(32, 8);
    // launch 0: rope table + x split (combined)
    prep_kernel<<<(BROWS * DMODEL) / 256, 256>>>(x, BROWS * DMODEL);
    // launches 1,2: weights needed by QKV gemm
    thalf_kernel<<<dim3(DMODEL / 32, KDIM / 32), tb>>>(Wq, wqh, DMODEL, 0);
    thalf_kv_kernel<<<dim3(HDIM / 32, KDIM / 32, 2), tb>>>(Wk, Wv);
    // launch 3: fused QKV projection + RoPE + scale + split  (ncu capture slot)
    gemm_kernel<true><<<dim3(18, BROWS / 128), 256, GEMM_SMEM>>>(nullptr, nullptr);
    // launch 4: Wo transpose (independent of attention)
    thalf_kernel<<<dim3(DMODEL / 32, KDIM / 32), tb>>>(Wo, woh, DMODEL, 0);
    // launch 5: attention
    dim3 ga(L_SEQ / 64, NHEADS, 2);
    attn_mma_kernel<<<ga, 128, ATTN_SMEM>>>(qh, ql, kh, vh, ath, atl);
    // launch 6: output projection + bias
    gemm_kernel<false><<<dim3(16, BROWS / 128), 256, GEMM_SMEM>>>(bo, out);
}

// round 17
// speedup vs baseline: 1.3701x; 1.2208x over previous
#include <cuda_runtime.h>
#include <cuda_fp16.h>
#include <math.h>
#include <stdint.h>

#define L_SEQ   2048
#define DMODEL  2048
#define NHEADS  16
#define HDIM    128
#define WINDOW  512
#define BROWS   4096   // B * L
#define KDIM    2048

typedef __half h16;

// ================= scratch =================
__device__ float g_cs[L_SEQ * 64];          // (cos,sin) interleaved
__device__ h16 g_xh[BROWS * DMODEL];
__device__ h16 g_xl[BROWS * DMODEL];
__device__ h16 g_qh[BROWS * DMODEL];
__device__ h16 g_ql[BROWS * DMODEL];
__device__ h16 g_kh[BROWS * HDIM];
__device__ h16 g_vh[BROWS * HDIM];
__device__ h16 g_ath[BROWS * DMODEL];       // attention out, fp16 (single precision level)
__device__ h16 g_wqt_h[DMODEL * KDIM];
__device__ h16 g_wot_h[DMODEL * KDIM];
__device__ h16 g_wkvt_h[256 * KDIM];

// ================= helpers =================
__device__ __forceinline__ uint32_t smem_u32(const void* p) {
    uint32_t a;
    asm("{ .reg .u64 t; cvta.to.shared.u64 t, %1; cvt.u32.u64 %0, t; }" : "=r"(a) : "l"(p));
    return a;
}
#define CP_ASYNC16(saddr, gptr) \
    asm volatile("cp.async.cg.shared.global [%0], [%1], 16;" :: "r"(saddr), "l"(gptr))
#define CP_COMMIT()  asm volatile("cp.async.commit_group;" ::: "memory")
#define CP_WAIT0()   asm volatile("cp.async.wait_group 0;" ::: "memory")
#define CP_WAIT1()   asm volatile("cp.async.wait_group 1;" ::: "memory")
#define CP_WAIT2()   asm volatile("cp.async.wait_group 2;" ::: "memory")

#define LDMATRIX_X4(r0, r1, r2, r3, addr) \
    asm volatile("ldmatrix.sync.aligned.m8n8.x4.shared.b16 {%0,%1,%2,%3}, [%4];" \
        : "=r"(r0), "=r"(r1), "=r"(r2), "=r"(r3) : "r"(addr))

#define LDMATRIX_X4_T(r0, r1, r2, r3, addr) \
    asm volatile("ldmatrix.sync.aligned.m8n8.x4.trans.shared.b16 {%0,%1,%2,%3}, [%4];" \
        : "=r"(r0), "=r"(r1), "=r"(r2), "=r"(r3) : "r"(addr))

#define MMA_F16(c, a, b) \
    asm volatile("mma.sync.aligned.m16n8k16.row.col.f32.f16.f16.f32 " \
        "{%0,%1,%2,%3}, {%4,%5,%6,%7}, {%8,%9}, {%0,%1,%2,%3};" \
        : "+f"((c)[0]), "+f"((c)[1]), "+f"((c)[2]), "+f"((c)[3]) \
        : "r"((a)[0]), "r"((a)[1]), "r"((a)[2]), "r"((a)[3]), "r"((b)[0]), "r"((b)[1]))

__device__ __forceinline__ uint32_t pack_split(float a, float b, uint32_t& lo) {
    __half2 h = __floats2half2_rn(a, b);
    __half2 l = __floats2half2_rn(a - __low2float(h), b - __high2float(h));
    lo = *(uint32_t*)&l;
    return *(uint32_t*)&h;
}

// ================= prep kernels =================
__global__ void prep_kernel(const float* __restrict__ in, int n) {
    int idx = blockIdx.x * blockDim.x + threadIdx.x;
    if (idx < L_SEQ * 32) {
        int pos = idx >> 5;
        int i = idx & 31;
        double inv = exp(-log(10000.0) * ((double)(2 * i) / 64.0));
        double th = (double)pos * inv;
        g_cs[pos * 64 + i * 2 + 0] = (float)cos(th);
        g_cs[pos * 64 + i * 2 + 1] = (float)sin(th);
    }
    if (idx < n) {
        float v = in[idx];
        h16 h = __float2half_rn(v);
        g_xh[idx] = h;
        g_xl[idx] = __float2half_rn(v - __half2float(h));
    }
}

__global__ void thalf_kernel(const float* __restrict__ W,
                             h16* __restrict__ Th, int N, int ro) {
    __shared__ float tile[32][33];
    int n0 = blockIdx.x * 32, k0 = blockIdx.y * 32;
    int tx = threadIdx.x, ty = threadIdx.y;
    #pragma unroll
    for (int i = ty; i < 32; i += 8)
        tile[i][tx] = W[(size_t)(k0 + i) * N + n0 + tx];
    __syncthreads();
    #pragma unroll
    for (int i = ty; i < 32; i += 8)
        Th[(size_t)(ro + n0 + i) * KDIM + k0 + tx] = __float2half_rn(tile[tx][i]);
}

__global__ void thalf_kv_kernel(const float* __restrict__ Wk,
                                const float* __restrict__ Wv) {
    __shared__ float tile[32][33];
    const float* W = blockIdx.z ? Wv : Wk;
    int ro = blockIdx.z ? 128 : 0;
    int n0 = blockIdx.x * 32, k0 = blockIdx.y * 32;
    int tx = threadIdx.x, ty = threadIdx.y;
    #pragma unroll
    for (int i = ty; i < 32; i += 8)
        tile[i][tx] = W[(size_t)(k0 + i) * HDIM + n0 + tx];
    __syncthreads();
    #pragma unroll
    for (int i = ty; i < 32; i += 8)
        g_wkvt_h[(size_t)(ro + n0 + i) * KDIM + k0 + tx] = __float2half_rn(tile[tx][i]);
}

// ===== mma.sync fp16 GEMM, K32 chunks, 3-stage =====
// QKV=true : 2-pass (x-hi + x-lo), fused rope/scale/split epilogue.
// QKV=false: 1-pass (ath only) O-projection with bias -> fp32 out.
template <bool QKV>
__global__ void __launch_bounds__(256, 2)
gemm_kernel(const float* __restrict__ bias, float* __restrict__ Cout) {
    extern __shared__ char smem[];
    const uint32_t smb = smem_u32(smem);
    const int tid = threadIdx.x;
    const int wid = tid >> 5;
    const int lane = tid & 31;
    const int wm = wid >> 1;
    const int wn = wid & 1;
    const uint32_t midx = lane >> 3;
    const uint32_t rsel = lane & 7;

    const int m0 = blockIdx.y * 128;
    const h16* Ah = QKV ? g_xh : g_ath;
    const h16* Al = g_xl;                      // used only when QKV
    const h16* Bh;
    int n0;
    h16 *OutH = nullptr, *OutL = nullptr;
    int strideO = 0, colBase = 0;
    bool do_rope = false, do_scale = false;
    if (QKV) {
        if ((int)blockIdx.x < 16) {
            Bh = g_wqt_h; n0 = blockIdx.x * 128;
            OutH = g_qh; OutL = g_ql; strideO = DMODEL; colBase = n0;
            do_rope = true; do_scale = true;
        } else if (blockIdx.x == 16) {
            Bh = g_wkvt_h; n0 = 0;
            OutH = g_kh; OutL = nullptr; strideO = HDIM; colBase = 0; do_rope = true;
        } else {
            Bh = g_wkvt_h; n0 = 128;
            OutH = g_vh; OutL = nullptr; strideO = HDIM; colBase = 0; do_rope = false;
        }
    } else {
        Bh = g_wot_h; n0 = blockIdx.x * 128;
    }

    const h16* srcs[3] = {
        Ah + (size_t)m0 * KDIM, Al + (size_t)m0 * KDIM, Bh + (size_t)n0 * KDIM };

    const int fr = tid >> 2;
    const uint32_t fkt = (uint32_t)(tid & 3);
    const int fc0 = (tid & 3) * 8;

    auto fill = [&](int kc, uint32_t sbase) {
        #pragma unroll
        for (int m = 0; m < 3; m++) {
            if (!QKV && m == 1) continue;   // no A-lo for O-projection
            #pragma unroll
            for (int half = 0; half < 2; half++) {
                int rr = fr + half * 64;
                uint32_t off = ((uint32_t)(rr >> 3) * 4 + fkt) * 128
                             + ((uint32_t)((rr & 7) ^ fkt) * 16);
                CP_ASYNC16(sbase + m * 8192 + off,
                           srcs[m] + (size_t)rr * KDIM + kc * 32 + fc0);
            }
        }
    };

    float acc[2][8][4];
    #pragma unroll
    for (int i = 0; i < 2; i++)
        #pragma unroll
        for (int j = 0; j < 8; j++)
            #pragma unroll
            for (int c = 0; c < 4; c++) acc[i][j][c] = 0.0f;

    fill(0, smb);          CP_COMMIT();
    fill(1, smb + 24576);  CP_COMMIT();

    const int NK = KDIM / 32;
    for (int kc = 0; kc < NK; kc++) {
        if (kc + 1 < NK) CP_WAIT1(); else CP_WAIT0();
        __syncthreads();
        if (kc + 2 < NK) {
            fill(kc + 2, smb + ((kc + 2) % 3) * 24576);
            CP_COMMIT();
        }

        const uint32_t sb = smb + (kc % 3) * 24576;
        const uint32_t aBaseH = sb;
        const uint32_t aBaseL = sb + 8192;
        const uint32_t bBaseH = sb + 16384;

        #pragma unroll
        for (int kt = 0; kt < 2; kt++) {
            uint32_t aH[2][4], aL[2][4], bF[8][2];
            const uint32_t TkA = (uint32_t)(kt * 2) + (midx >> 1);
            const uint32_t TkB = (uint32_t)(kt * 2) + (midx & 1);
            #pragma unroll
            for (int nj = 0; nj < 4; nj++) {
                uint32_t Tn = (uint32_t)(wn * 8 + nj * 2) + (midx >> 1);
                uint32_t addr = bBaseH + (Tn * 4 + TkB) * 128 + ((rsel ^ TkB) * 16);
                uint32_t r0, r1, r2, r3;
                LDMATRIX_X4(r0, r1, r2, r3, addr);
                bF[nj * 2][0] = r0; bF[nj * 2][1] = r1;
                bF[nj * 2 + 1][0] = r2; bF[nj * 2 + 1][1] = r3;
            }
            #pragma unroll
            for (int mi = 0; mi < 2; mi++) {
                uint32_t Tm = (uint32_t)(wm * 4 + mi * 2) + (midx & 1);
                uint32_t addr = aBaseH + (Tm * 4 + TkA) * 128 + ((rsel ^ TkA) * 16);
                LDMATRIX_X4(aH[mi][0], aH[mi][1], aH[mi][2], aH[mi][3], addr);
            }
            if (QKV) {
                #pragma unroll
                for (int mi = 0; mi < 2; mi++) {
                    uint32_t Tm = (uint32_t)(wm * 4 + mi * 2) + (midx & 1);
                    uint32_t addr = aBaseL + (Tm * 4 + TkA) * 128 + ((rsel ^ TkA) * 16);
                    LDMATRIX_X4(aL[mi][0], aL[mi][1], aL[mi][2], aL[mi][3], addr);
                }
            }
            #pragma unroll
            for (int mi = 0; mi < 2; mi++)
                #pragma unroll
                for (int nf = 0; nf < 8; nf++)
                    MMA_F16(acc[mi][nf], aH[mi], bF[nf]);
            if (QKV) {
                #pragma unroll
                for (int mi = 0; mi < 2; mi++)
                    #pragma unroll
                    for (int nf = 0; nf < 8; nf++)
                        MMA_F16(acc[mi][nf], aL[mi], bF[nf]);
            }
        }
        __syncthreads();
    }

    if (!QKV) {
        #pragma unroll
        for (int mi = 0; mi < 2; mi++) {
            int row = m0 + wm * 32 + mi * 16 + (lane >> 2);
            #pragma unroll
            for (int nf = 0; nf < 8; nf++) {
                int col = n0 + wn * 64 + nf * 8 + (lane & 3) * 2;
                float b0 = bias[col], b1 = bias[col + 1];
                float2 v0, v1;
                v0.x = acc[mi][nf][0] + b0; v0.y = acc[mi][nf][1] + b1;
                v1.x = acc[mi][nf][2] + b0; v1.y = acc[mi][nf][3] + b1;
                *(float2*)&Cout[(size_t)row * DMODEL + col] = v0;
                *(float2*)&Cout[(size_t)(row + 8) * DMODEL + col] = v1;
            }
        }
        return;
    }

    if (do_rope && wn == 0) {
        #pragma unroll
        for (int mi = 0; mi < 2; mi++) {
            int r0 = m0 + wm * 32 + mi * 16 + (lane >> 2);
            int pos0 = r0 & (L_SEQ - 1);
            int pos1 = (r0 + 8) & (L_SEQ - 1);
            #pragma unroll
            for (int nf = 0; nf < 4; nf++) {
                int c = nf * 8 + (lane & 3) * 2;
                float2 csA0 = *(float2*)&g_cs[pos0 * 64 + c * 2];
                float2 csB0 = *(float2*)&g_cs[pos0 * 64 + c * 2 + 2];
                float2 csA1 = *(float2*)&g_cs[pos1 * 64 + c * 2];
                float2 csB1 = *(float2*)&g_cs[pos1 * 64 + c * 2 + 2];
                float x1, x2;
                x1 = acc[mi][nf][0]; x2 = acc[mi][nf + 4][0];
                acc[mi][nf][0]     = x1 * csA0.x - x2 * csA0.y;
                acc[mi][nf + 4][0] = x1 * csA0.y + x2 * csA0.x;
                x1 = acc[mi][nf][1]; x2 = acc[mi][nf + 4][1];
                acc[mi][nf][1]     = x1 * csB0.x - x2 * csB0.y;
                acc[mi][nf + 4][1] = x1 * csB0.y + x2 * csB0.x;
                x1 = acc[mi][nf][2]; x2 = acc[mi][nf + 4][2];
                acc[mi][nf][2]     = x1 * csA1.x - x2 * csA1.y;
                acc[mi][nf + 4][2] = x1 * csA1.y + x2 * csA1.x;
                x1 = acc[mi][nf][3]; x2 = acc[mi][nf + 4][3];
                acc[mi][nf][3]     = x1 * csB1.x - x2 * csB1.y;
                acc[mi][nf + 4][3] = x1 * csB1.y + x2 * csB1.x;
            }
        }
    }

    if (do_scale) {
        const float sc = 0.08838834764831845f;
        #pragma unroll
        for (int mi = 0; mi < 2; mi++)
            #pragma unroll
            for (int nf = 0; nf < 8; nf++)
                #pragma unroll
                for (int c = 0; c < 4; c++) acc[mi][nf][c] *= sc;
    }

    #pragma unroll
    for (int mi = 0; mi < 2; mi++) {
        int row = m0 + wm * 32 + mi * 16 + (lane >> 2);
        #pragma unroll
        for (int nf = 0; nf < 8; nf++) {
            int cl = colBase + wn * 64 + nf * 8 + (lane & 3) * 2;
            uint32_t lo, hi;
            hi = pack_split(acc[mi][nf][0], acc[mi][nf][1], lo);
            *(uint32_t*)&OutH[(size_t)row * strideO + cl] = hi;
            if (OutL) *(uint32_t*)&OutL[(size_t)row * strideO + cl] = lo;
            hi = pack_split(acc[mi][nf][2], acc[mi][nf][3], lo);
            *(uint32_t*)&OutH[(size_t)(row + 8) * strideO + cl] = hi;
            if (OutL) *(uint32_t*)&OutL[(size_t)(row + 8) * strideO + cl] = lo;
        }
    }
}

// ======== attention: 64-row Q tiles, 128 threads, 3-stage KV, 2 CTAs/SM ========
__global__ void __launch_bounds__(128, 2)
attn_mma_kernel(const h16* __restrict__ Qh, const h16* __restrict__ Ql,
                const h16* __restrict__ Kh, const h16* __restrict__ Vh,
                h16* __restrict__ Oh) {
    extern __shared__ char smem[];
    const uint32_t smb = smem_u32(smem);
    const uint32_t STG = 32768;
    const int tid = threadIdx.x, wid = tid >> 5, lane = tid & 31;
    const uint32_t midx = lane >> 3, rsel = lane & 7;
    const int qt = blockIdx.x, h = blockIdx.y, b = blockIdx.z;
    const int q0 = qt * 64;
    const size_t qrow0 = (size_t)(b * L_SEQ + q0);

    {
        const h16* srcQ[2] = {
            Qh + qrow0 * DMODEL + h * HDIM, Ql + qrow0 * DMODEL + h * HDIM };
        #pragma unroll
        for (int m = 0; m < 2; m++) {
            uint32_t base = smb + m * STG;
            #pragma unroll
            for (int i = 0; i < 8; i++) {
                int cid = tid + i * 128;
                int r = cid >> 4, j = cid & 15;
                uint32_t off = ((uint32_t)(r >> 3) * 16 + j) * 128
                             + ((uint32_t)((r & 7) ^ (j & 7)) * 16);
                CP_ASYNC16(base + off, srcQ[m] + (size_t)r * DMODEL + j * 8);
            }
        }
        CP_COMMIT();
        CP_WAIT0();
        __syncthreads();
    }
    uint32_t qHf[8][4], qLf[8][4];
    {
        const uint32_t TmA = (uint32_t)(wid * 2) + (midx & 1);
        #pragma unroll
        for (int ks = 0; ks < 8; ks++) {
            uint32_t TkA = (uint32_t)(ks * 2) + (midx >> 1);
            uint32_t offA = (TmA * 16 + TkA) * 128 + ((rsel ^ (TkA & 7)) * 16);
            LDMATRIX_X4(qHf[ks][0], qHf[ks][1], qHf[ks][2], qHf[ks][3], smb + offA);
            LDMATRIX_X4(qLf[ks][0], qLf[ks][1], qLf[ks][2], qLf[ks][3], smb + STG + offA);
        }
    }
    __syncthreads();

    int t0 = q0 - (WINDOW - 1);
    if (t0 < 0) t0 = 0;
    t0 >>= 6;
    const int t1 = qt;
    const int tmask_lo = qt - 8;

    auto fill_kv = [&](int t) {
        const uint32_t sb = smb + (uint32_t)((t - t0) % 3) * STG;
        const size_t rowb = (size_t)(b * L_SEQ + t * 64);
        const h16* srcs[2] = { Kh + rowb * HDIM, Vh + rowb * HDIM };
        #pragma unroll
        for (int m = 0; m < 2; m++) {
            uint32_t base = sb + m * 16384;
            #pragma unroll
            for (int i = 0; i < 8; i++) {
                int cid = tid + i * 128;
                int r = cid >> 4, j = cid & 15;
                uint32_t off;
                if (m == 0)
                    off = ((uint32_t)(r >> 3) * 16 + j) * 128
                        + ((uint32_t)((r & 7) ^ (j & 7)) * 16);
                else
                    off = (uint32_t)r * 256 + ((uint32_t)(j ^ (r & 7)) * 16);
                CP_ASYNC16(base + off, srcs[m] + (size_t)r * HDIM + j * 8);
            }
        }
    };

    fill_kv(t0); CP_COMMIT();
    if (t0 + 1 <= t1) { fill_kv(t0 + 1); CP_COMMIT(); }

    float acc[16][4];
    #pragma unroll
    for (int i = 0; i < 16; i++)
        #pragma unroll
        for (int c = 0; c < 4; c++) acc[i][c] = 0.0f;
    float m0r = -1e30f, m1r = -1e30f, l0r = 0.0f, l1r = 0.0f;

    const int gR0 = q0 + wid * 16 + (lane >> 2);

    for (int t = t0; t <= t1; t++) {
        if (t + 2 <= t1) { fill_kv(t + 2); CP_COMMIT(); }
        int rem = t1 - t;
        if (rem >= 2) CP_WAIT2();
        else if (rem == 1) CP_WAIT1();
        else CP_WAIT0();
        __syncthreads();

        const uint32_t sKV = smb + (uint32_t)((t - t0) % 3) * STG;
        const uint32_t sKh = sKV;
        const uint32_t sVh = sKV + 16384;
        const int kbase = t * 64;

        float sc[8][4];
        #pragma unroll
        for (int i = 0; i < 8; i++)
            #pragma unroll
            for (int c = 0; c < 4; c++) sc[i][c] = 0.0f;

        #pragma unroll
        for (int ks = 0; ks < 8; ks++) {
            uint32_t bH[8][2];
            uint32_t TkB = (uint32_t)(ks * 2) + (midx & 1);
            #pragma unroll
            for (int nj = 0; nj < 4; nj++) {
                uint32_t Tn = (uint32_t)(nj * 2) + (midx >> 1);
                uint32_t off = (Tn * 16 + TkB) * 128 + ((rsel ^ (TkB & 7)) * 16);
                uint32_t r0, r1, r2, r3;
                LDMATRIX_X4(r0, r1, r2, r3, sKh + off);
                bH[nj * 2][0] = r0; bH[nj * 2][1] = r1;
                bH[nj * 2 + 1][0] = r2; bH[nj * 2 + 1][1] = r3;
            }
            #pragma unroll
            for (int nf = 0; nf < 8; nf++) MMA_F16(sc[nf], qHf[ks], bH[nf]);
            #pragma unroll
            for (int nf = 0; nf < 8; nf++) MMA_F16(sc[nf], qLf[ks], bH[nf]);
        }

        if (t == t1 || t == tmask_lo) {
            #pragma unroll
            for (int nf = 0; nf < 8; nf++) {
                int col = kbase + nf * 8 + (lane & 3) * 2;
                int d00 = gR0 - col, d01 = d00 - 1;
                int d10 = gR0 + 8 - col, d11 = d10 - 1;
                sc[nf][0] += (d00 >= 0 && d00 < WINDOW) ? 0.f : -1e9f;
                sc[nf][1] += (d01 >= 0 && d01 < WINDOW) ? 0.f : -1e9f;
                sc[nf][2] += (d10 >= 0 && d10 < WINDOW) ? 0.f : -1e9f;
                sc[nf][3] += (d11 >= 0 && d11 < WINDOW) ? 0.f : -1e9f;
            }
        }

        float mx0 = -1e30f, mx1 = -1e30f;
        #pragma unroll
        for (int nf = 0; nf < 8; nf++) {
            mx0 = fmaxf(mx0, fmaxf(sc[nf][0], sc[nf][1]));
            mx1 = fmaxf(mx1, fmaxf(sc[nf][2], sc[nf][3]));
        }
        mx0 = fmaxf(mx0, __shfl_xor_sync(0xffffffffu, mx0, 1));
        mx0 = fmaxf(mx0, __shfl_xor_sync(0xffffffffu, mx0, 2));
        mx1 = fmaxf(mx1, __shfl_xor_sync(0xffffffffu, mx1, 1));
        mx1 = fmaxf(mx1, __shfl_xor_sync(0xffffffffu, mx1, 2));
        float mn0 = fmaxf(m0r, mx0), mn1 = fmaxf(m1r, mx1);
        float corr0 = __expf(m0r - mn0), corr1 = __expf(m1r - mn1);
        m0r = mn0; m1r = mn1;
        float rs0 = 0.f, rs1 = 0.f;
        #pragma unroll
        for (int nf = 0; nf < 8; nf++) {
            sc[nf][0] = __expf(sc[nf][0] - mn0);
            sc[nf][1] = __expf(sc[nf][1] - mn0);
            sc[nf][2] = __expf(sc[nf][2] - mn1);
            sc[nf][3] = __expf(sc[nf][3] - mn1);
            rs0 += sc[nf][0] + sc[nf][1];
            rs1 += sc[nf][2] + sc[nf][3];
        }
        rs0 += __shfl_xor_sync(0xffffffffu, rs0, 1);
        rs0 += __shfl_xor_sync(0xffffffffu, rs0, 2);
        rs1 += __shfl_xor_sync(0xffffffffu, rs1, 1);
        rs1 += __shfl_xor_sync(0xffffffffu, rs1, 2);
        l0r = l0r * corr0 + rs0;
        l1r = l1r * corr1 + rs1;
        #pragma unroll
        for (int nf = 0; nf < 16; nf++) {
            acc[nf][0] *= corr0; acc[nf][1] *= corr0;
            acc[nf][2] *= corr1; acc[nf][3] *= corr1;
        }

        uint32_t aPh[4][4], aPl[4][4];
        #pragma unroll
        for (int kt2 = 0; kt2 < 4; kt2++) {
            #pragma unroll
            for (int half = 0; half < 2; half++) {
                int nf = kt2 * 2 + half;
                uint32_t lo01, lo23;
                uint32_t hi01 = pack_split(sc[nf][0], sc[nf][1], lo01);
                uint32_t hi23 = pack_split(sc[nf][2], sc[nf][3], lo23);
                aPh[kt2][half * 2 + 0] = hi01;
                aPh[kt2][half * 2 + 1] = hi23;
                aPl[kt2][half * 2 + 0] = lo01;
                aPl[kt2][half * 2 + 1] = lo23;
            }
        }

        #pragma unroll
        for (int kt2 = 0; kt2 < 4; kt2++) {
            uint32_t bb[16][2];
            uint32_t krow = (uint32_t)(kt2 * 16) + ((midx & 1) * 8) + rsel;
            #pragma unroll
            for (int nj = 0; nj < 8; nj++) {
                uint32_t j = (uint32_t)(nj * 2) + (midx >> 1);
                uint32_t off = krow * 256 + ((j ^ rsel) * 16);
                uint32_t r0, r1, r2, r3;
                LDMATRIX_X4_T(r0, r1, r2, r3, sVh + off);
                bb[nj * 2][0] = r0; bb[nj * 2][1] = r1;
                bb[nj * 2 + 1][0] = r2; bb[nj * 2 + 1][1] = r3;
            }
            #pragma unroll
            for (int nf = 0; nf < 16; nf++) MMA_F16(acc[nf], aPh[kt2], bb[nf]);
            #pragma unroll
            for (int nf = 0; nf < 16; nf++) MMA_F16(acc[nf], aPl[kt2], bb[nf]);
        }
        __syncthreads();
    }

    float inv0 = 1.0f / l0r, inv1 = 1.0f / l1r;
    size_t row0 = qrow0 + wid * 16 + (lane >> 2);
    size_t row1 = row0 + 8;
    #pragma unroll
    for (int nf = 0; nf < 16; nf++) {
        int col = h * HDIM + nf * 8 + (lane & 3) * 2;
        __half2 h01 = __floats2half2_rn(acc[nf][0] * inv0, acc[nf][1] * inv0);
        __half2 h23 = __floats2half2_rn(acc[nf][2] * inv1, acc[nf][3] * inv1);
        *(uint32_t*)&Oh[row0 * DMODEL + col] = *(uint32_t*)&h01;
        *(uint32_t*)&Oh[row1 * DMODEL + col] = *(uint32_t*)&h23;
    }
}

// ================= launch =================
extern "C" void kernel_launch(void* const* d_in, const int* in_sizes, int n_in,
                              void* d_out, int out_size) {
    const float* x  = (const float*)d_in[0];
    const float* Wq = (const float*)d_in[1];
    const float* Wk = (const float*)d_in[2];
    const float* Wv = (const float*)d_in[3];
    const float* Wo = (const float*)d_in[4];
    const float* bo = (const float*)d_in[5];
    float* out = (float*)d_out;

    h16 *qh, *ql, *kh, *vh, *ath, *wqh, *woh;
    cudaGetSymbolAddress((void**)&qh,  g_qh);
    cudaGetSymbolAddress((void**)&ql,  g_ql);
    cudaGetSymbolAddress((void**)&kh,  g_kh);
    cudaGetSymbolAddress((void**)&vh,  g_vh);
    cudaGetSymbolAddress((void**)&ath, g_ath);
    cudaGetSymbolAddress((void**)&wqh, g_wqt_h);
    cudaGetSymbolAddress((void**)&woh, g_wot_h);

    const int GEMM_SMEM = 73728;    // 3 stages x 24KB
    cudaFuncSetAttribute(gemm_kernel<true>,
                         cudaFuncAttributeMaxDynamicSharedMemorySize, GEMM_SMEM);
    cudaFuncSetAttribute(gemm_kernel<false>,
                         cudaFuncAttributeMaxDynamicSharedMemorySize, GEMM_SMEM);
    const int ATTN_SMEM = 98304;    // 3 KV stages x 32KB
    cudaFuncSetAttribute(attn_mma_kernel,
                         cudaFuncAttributeMaxDynamicSharedMemorySize, ATTN_SMEM);

    dim3 tb(32, 8);
    // launch 0: rope table + x split (combined)
    prep_kernel<<<(BROWS * DMODEL) / 256, 256>>>(x, BROWS * DMODEL);
    // launches 1,2: weights needed by QKV gemm
    thalf_kernel<<<dim3(DMODEL / 32, KDIM / 32), tb>>>(Wq, wqh, DMODEL, 0);
    thalf_kv_kernel<<<dim3(HDIM / 32, KDIM / 32, 2), tb>>>(Wk, Wv);
    // launch 3: fused QKV projection + RoPE + scale + split  (ncu capture slot)
    gemm_kernel<true><<<dim3(18, BROWS / 128), 256, GEMM_SMEM>>>(nullptr, nullptr);
    // launch 4: Wo transpose (independent of attention)
    thalf_kernel<<<dim3(DMODEL / 32, KDIM / 32), tb>>>(Wo, woh, DMODEL, 0);
    // launch 5: attention -> fp16 out (single precision level)
    dim3 ga(L_SEQ / 64, NHEADS, 2);
    attn_mma_kernel<<<ga, 128, ATTN_SMEM>>>(qh, ql, kh, vh, ath);
    // launch 6: output projection + bias (1-pass)
    gemm_kernel<false><<<dim3(16, BROWS / 128), 256, GEMM_SMEM>>>(bo, out);
}